// round 16
// baseline (speedup 1.0000x reference)
#include <cuda_runtime.h>
#include <cstdint>

#define DEV static __device__ __forceinline__
typedef unsigned __int128 u128;

__device__ unsigned char g_group[10000];
__device__ float g_bias[10000];
__device__ int g_cfg_done = 0;
__device__ int g_out_done = 0;

// ---------------- PCG64 (numpy default_rng) ----------------
DEV u128 PCG_MULT() {
  return (((u128)0x2360ED051FC65DA4ULL) << 64) | 0x4385DF649FCCF645ULL;
}
DEV uint32_t hashmix(uint32_t v, uint32_t& hc) {
  v ^= hc; hc *= 0x931e8875u; v *= hc; v ^= v >> 16; return v;
}
DEV uint32_t mix32(uint32_t x, uint32_t y) {
  uint32_t r = 0xca01f9ddu * x - 0x4973f715u * y; r ^= r >> 16; return r;
}
DEV void pcg_seed(u128& state, u128& inc) {
  uint32_t pool[4]; uint32_t hc = 0x43b0d7e5u;
  for (int i = 0; i < 4; ++i) pool[i] = hashmix(0u, hc);
  for (int s = 0; s < 4; ++s)
    for (int d2 = 0; d2 < 4; ++d2)
      if (s != d2) pool[d2] = mix32(pool[d2], hashmix(pool[s], hc));
  uint32_t hc2 = 0x8b51f9ddu; uint32_t w[8];
  for (int i = 0; i < 8; ++i) {
    uint32_t dv = pool[i & 3];
    dv ^= hc2; hc2 *= 0x58f38dedu; dv *= hc2; dv ^= dv >> 16; w[i] = dv;
  }
  u128 initstate = (((u128)((uint64_t)w[0] | ((uint64_t)w[1] << 32))) << 64) |
                   ((uint64_t)w[2] | ((uint64_t)w[3] << 32));
  u128 initseq   = (((u128)((uint64_t)w[4] | ((uint64_t)w[5] << 32))) << 64) |
                   ((uint64_t)w[6] | ((uint64_t)w[7] << 32));
  inc = (initseq << 1) | (u128)1;
  state = inc; state += initstate;
  state = state * PCG_MULT() + inc;
}
DEV u128 pcg_advance(u128 state, u128 inc, uint64_t delta) {
  u128 cm = PCG_MULT(), cp = inc, am = (u128)1, ap = (u128)0;
  while (delta) {
    if (delta & 1) { am = am * cm; ap = ap * cm + cp; }
    cp = (cm + (u128)1) * cp; cm = cm * cm; delta >>= 1;
  }
  return am * state + ap;
}
DEV uint64_t pcg_out(u128 st) {
  unsigned rot = (unsigned)(st >> 122);
  uint64_t x = (uint64_t)(st >> 64) ^ (uint64_t)st;
  return (x >> rot) | (x << ((64 - rot) & 63));
}

// ---------------- helpers ----------------
DEV void f4add(float4& a, const float4 v) {
  a.x += v.x; a.y += v.y; a.z += v.z; a.w += v.w;
}
DEV unsigned int f2ord(float f) {
  unsigned int b = __float_as_uint(f);
  return (b & 0x80000000u) ? ~b : (b | 0x80000000u);
}
DEV uint32_t smem_u32(const void* p) {
  uint32_t a;
  asm("{ .reg .u64 tmp; cvta.to.shared.u64 tmp, %1; cvt.u32.u64 %0, tmp; }"
      : "=r"(a) : "l"(p));
  return a;
}
DEV void mbar_init(uint32_t mbar, uint32_t count) {
  asm volatile("mbarrier.init.shared.b64 [%0], %1;" :: "r"(mbar), "r"(count) : "memory");
}
DEV void mbar_expect_tx(uint32_t mbar, uint32_t bytes) {
  asm volatile("mbarrier.arrive.expect_tx.shared.b64 _, [%0], %1;"
               :: "r"(mbar), "r"(bytes) : "memory");
}
DEV void bulk_copy(uint32_t dst_smem, const void* src, uint32_t bytes, uint32_t mbar) {
  asm volatile("cp.async.bulk.shared::cta.global.mbarrier::complete_tx::bytes "
               "[%0], [%1], %2, [%3];"
               :: "r"(dst_smem), "l"(src), "r"(bytes), "r"(mbar) : "memory");
}
DEV void mbar_wait(uint32_t mbar, uint32_t parity) {
  asm volatile(
      "{\n\t.reg .pred P;\n"
      "W%=:\n\t"
      "mbarrier.try_wait.parity.shared.b64 P, [%0], %1;\n\t"
      "@P bra D%=;\n\t"
      "bra W%=;\n"
      "D%=:\n\t}"
      :: "r"(mbar), "r"(parity) : "memory");
}

// ---------------- conv variants (512 threads, 16 conv values/thread total) ----------------
// scalar path (D=1,2): elements e = t + i*512
template <int D>
DEV void conv2K_s(const float* S, int t, float* r7, float* r9) {
#pragma unroll
  for (int i = 0; i < 8; ++i) {
    int l = t + i * 512 + 128;
    float a = S[l - 3 * D];
    a += S[l - 2 * D]; a += S[l - D]; a += S[l]; a += S[l + D];
    a += S[l + 2 * D]; a += S[l + 3 * D];
    r7[i] = a;
    r9[i] = a + S[l - 4 * D] + S[l + 4 * D];
  }
}
// vector path (D multiple of 4): thread owns elements 4*(t+g*512)..+3; float4 taps
template <int D>
DEV void conv2K_v(const float* S, int t, float4* q7, float4* q9) {
  const float4* S4 = (const float4*)S;
  const int DS = D / 4;
#pragma unroll
  for (int g = 0; g < 2; ++g) {
    int base = t + g * 512 + 32;        // (4*(t+g*512) + 128) / 4
    float4 a = S4[base - 3 * DS];
    f4add(a, S4[base - 2 * DS]); f4add(a, S4[base - DS]); f4add(a, S4[base]);
    f4add(a, S4[base + DS]); f4add(a, S4[base + 2 * DS]); f4add(a, S4[base + 3 * DS]);
    q7[g] = a;
    float4 b = a;
    f4add(b, S4[base - 4 * DS]); f4add(b, S4[base + 4 * DS]);
    q9[g] = b;
  }
}

struct __align__(128) MainSmem {
  float S[4352];            // pad128 | row 4096 | pad128 (never dirtied)
  float stage[4][4096];     // 64KB bulk-copy staging; reused as U after load
  unsigned long long mbar[4];
  unsigned int hist[256];
  unsigned int wt[16];
  int sel[2];
  float redA[16], redB[16], sumA[16], sumB[16];
  float pivots[2];
  float mres[12], tres[12];
  int cnt12[12];
  int rci[16];
};

// cold exact path: radix-select rank 1351 over keys in U, then count(<=key);
// flag = count < 2704 i.e. v[1351] < v[2703]. 512 threads.
__device__ __noinline__ void fallback_select(unsigned int* U, unsigned int* hist,
                                             unsigned int* wt, int* sel, int* rci,
                                             int t, float* tres) {
  int lane = t & 31, wid = t >> 5;
  if (t < 256) hist[t] = 0;
  __syncthreads();
  for (int i = 0; i < 8; ++i)
    atomicAdd(&hist[U[t + i * 512] >> 24], 1u);
  __syncthreads();

#define SCAN_SELECT(rr)                                                        \
  {                                                                            \
    unsigned int oa = (t < 256) ? hist[t] : 0u; unsigned int a = oa;           \
    for (int o = 1; o < 32; o <<= 1) {                                         \
      unsigned int na = __shfl_up_sync(0xffffffffu, a, o);                     \
      if (lane >= o) a += na;                                                  \
    }                                                                          \
    if (lane == 31 && wid < 8) wt[wid] = a;                                    \
    __syncthreads();                                                           \
    if (wid == 0) {                                                            \
      unsigned int va = (lane < 8) ? wt[lane] : 0u;                            \
      for (int o = 1; o < 8; o <<= 1) {                                        \
        unsigned int na = __shfl_up_sync(0xffffffffu, va, o);                  \
        if (lane >= o) va += na;                                               \
      }                                                                        \
      if (lane < 8) wt[lane] = va;                                             \
    }                                                                          \
    __syncthreads();                                                           \
    if (t < 256) {                                                             \
      a += wid ? wt[wid - 1] : 0u;                                             \
      unsigned int lo = a - oa;                                                \
      if ((unsigned)(rr) >= lo && (unsigned)(rr) < a) { sel[0] = t; sel[1] = (int)lo; } \
    }                                                                          \
    __syncthreads();                                                           \
  }

  int rA = 1351; unsigned int pA = 0;
  SCAN_SELECT(rA);
  pA = ((unsigned int)sel[0]) << 24; rA -= sel[1];

  for (int p = 1; p < 4; ++p) {
    int shift = 24 - 8 * p;
    unsigned int maskHi = 0xFFFFFFFFu << (32 - 8 * p);
    if (t < 256) hist[t] = 0;
    __syncthreads();
    for (int i = 0; i < 8; ++i) {
      unsigned int key = U[t + i * 512];
      if (((key ^ pA) & maskHi) == 0)
        atomicAdd(&hist[(key >> shift) & 255u], 1u);
    }
    __syncthreads();
    SCAN_SELECT(rA);
    pA |= ((unsigned int)sel[0]) << shift; rA -= sel[1];
  }

  int cnt = 0;
  for (int i = 0; i < 8; ++i) cnt += (U[t + i * 512] <= pA) ? 1 : 0;
  for (int o = 16; o; o >>= 1) cnt += __shfl_xor_sync(0xffffffffu, cnt, o);
  if (lane == 0) rci[wid] = cnt;
  __syncthreads();
  if (t == 0) {
    int total = 0;
    for (int i = 0; i < 16; ++i) total += rci[i];
    *tres = (total < 2704) ? 1.0f : 0.0f;
  }
  __syncthreads();
#undef SCAN_SELECT
}

// hot path per dilation: conv -> warp reduce -> warp0 reduces 16 partials,
// publishes max + pivot(mean) -> count(<=pivot) via shared atomics; count in
// [1352,2703] certifies v[1351] <= p < v[2703] => flag=1 exactly.
DEV void process_dilation(MainSmem* sm, int dexp, int t, int lane, int wid) {
  float* S = sm->S;
  float4 q7[2], q9[2];
  float* r7 = (float*)q7;
  float* r9 = (float*)q9;
  switch (dexp) {
    case 0:  conv2K_s<1>(S, t, r7, r9);  break;
    case 1:  conv2K_s<2>(S, t, r7, r9);  break;
    case 2:  conv2K_v<4>(S, t, q7, q9);  break;
    case 3:  conv2K_v<8>(S, t, q7, q9);  break;
    case 4:  conv2K_v<16>(S, t, q7, q9); break;
    default: conv2K_v<32>(S, t, q7, q9); break;
  }

  float mxA = r7[0], mxB = r9[0], smA = r7[0], smB = r9[0];
#pragma unroll
  for (int i = 1; i < 8; ++i) {
    mxA = fmaxf(mxA, r7[i]); smA += r7[i];
    mxB = fmaxf(mxB, r9[i]); smB += r9[i];
  }
  for (int o = 16; o; o >>= 1) {
    mxA = fmaxf(mxA, __shfl_xor_sync(0xffffffffu, mxA, o));
    mxB = fmaxf(mxB, __shfl_xor_sync(0xffffffffu, mxB, o));
    smA += __shfl_xor_sync(0xffffffffu, smA, o);
    smB += __shfl_xor_sync(0xffffffffu, smB, o);
  }
  if (lane == 0) {
    sm->redA[wid] = mxA; sm->redB[wid] = mxB;
    sm->sumA[wid] = smA; sm->sumB[wid] = smB;
  }
  __syncthreads();

  // warp 0 reduces the 16 partials and publishes results
  if (wid == 0) {
    float a = (lane < 16) ? sm->redA[lane] : -3.402823466e38f;
    float b = (lane < 16) ? sm->redB[lane] : -3.402823466e38f;
    float c = (lane < 16) ? sm->sumA[lane] : 0.f;
    float d = (lane < 16) ? sm->sumB[lane] : 0.f;
    for (int o = 8; o; o >>= 1) {
      a = fmaxf(a, __shfl_xor_sync(0xffffffffu, a, o));
      b = fmaxf(b, __shfl_xor_sync(0xffffffffu, b, o));
      c += __shfl_xor_sync(0xffffffffu, c, o);
      d += __shfl_xor_sync(0xffffffffu, d, o);
    }
    if (lane == 0) {
      sm->mres[dexp] = a; sm->mres[6 + dexp] = b;
      sm->pivots[0] = c * (1.0f / 4096.0f);
      sm->pivots[1] = d * (1.0f / 4096.0f);
    }
  }
  __syncthreads();

  float pA = sm->pivots[0], pB = sm->pivots[1];
  int cA = 0, cB = 0;
#pragma unroll
  for (int i = 0; i < 8; ++i) {
    cA += (r7[i] <= pA) ? 1 : 0;
    cB += (r9[i] <= pB) ? 1 : 0;
  }
  for (int o = 16; o; o >>= 1) {
    cA += __shfl_xor_sync(0xffffffffu, cA, o);
    cB += __shfl_xor_sync(0xffffffffu, cB, o);
  }
  if (lane == 0) {
    atomicAdd(&sm->cnt12[2 * dexp], cA);
    atomicAdd(&sm->cnt12[2 * dexp + 1], cB);
  }
  __syncthreads();

  int tA = sm->cnt12[2 * dexp], tB = sm->cnt12[2 * dexp + 1];
  bool okA = (tA >= 1352 && tA <= 2703);
  bool okB = (tB >= 1352 && tB <= 2703);
  if (t == 0) {
    if (okA) sm->tres[dexp] = 1.0f;
    if (okB) sm->tres[6 + dexp] = 1.0f;
  }
  if (okA && okB) return;

  unsigned int* U = (unsigned int*)sm->stage;   // staging is free after load
  if (!okA) {
#pragma unroll
    for (int i = 0; i < 8; ++i) U[t + i * 512] = f2ord(r7[i]);
    __syncthreads();
    fallback_select(U, sm->hist, sm->wt, sm->sel, sm->rci, t, &sm->tres[dexp]);
  }
  if (!okB) {
#pragma unroll
    for (int i = 0; i < 8; ++i) U[t + i * 512] = f2ord(r9[i]);
    __syncthreads();
    fallback_select(U, sm->hist, sm->wt, sm->sel, sm->rci, t, &sm->tres[6 + dexp]);
  }
}

// ---------------- self-contained config blocks (512 threads) ----------------
// Candidate c (0..10047) is u32 draw #(10000+c) => u64 #(5000+c/2), low first.
// Lemire rng_excl=6: accept iff low32(u*6) >= 4; value = hi32(u*6).
DEV void cfg_group_block(MainSmem* sm, int t) {
  u128 s0, inc; pcg_seed(s0, inc);
  const int PER = 20;
  int base = t * PER;
  unsigned char acc[PER], cnd[PER];
  int cnt = 0;
  u128 st = pcg_advance(s0, inc, (uint64_t)(5000 + (base >> 1)) + 1);
  for (int k2 = 0; k2 < PER / 2; ++k2) {
    uint64_t v = pcg_out(st); st = st * PCG_MULT() + inc;
    int c0 = base + 2 * k2;
    unsigned long long m0 = (unsigned long long)(uint32_t)v * 6ull;
    unsigned long long m1 = (unsigned long long)(uint32_t)(v >> 32) * 6ull;
    unsigned char a0 = (c0 < 10048) && ((unsigned int)m0 >= 4u);
    unsigned char a1 = (c0 + 1 < 10048) && ((unsigned int)m1 >= 4u);
    acc[2 * k2] = a0;     cnd[2 * k2] = (unsigned char)(m0 >> 32);
    acc[2 * k2 + 1] = a1; cnd[2 * k2 + 1] = (unsigned char)(m1 >> 32);
    cnt += a0 + a1;
  }
  int lane = t & 31, wid = t >> 5;
  int iv = cnt;
  for (int o = 1; o < 32; o <<= 1) {
    int n = __shfl_up_sync(0xffffffffu, iv, o);
    if (lane >= o) iv += n;
  }
  if (lane == 31) sm->rci[wid] = iv;
  __syncthreads();
  int woff = 0;
  for (int i = 0; i < wid; ++i) woff += sm->rci[i];
  int e0 = woff + iv - cnt;

  if (cnt > 0 && e0 < 10000) {
    uint64_t uidx = (uint64_t)(e0 >> 1);
    u128 st2 = pcg_advance(s0, inc, uidx + 1);
    uint64_t v2 = pcg_out(st2);
    int excl = e0;
    for (int k = 0; k < PER; ++k) {
      if (acc[k]) {
        if (excl < 10000) {
          uint64_t need = (uint64_t)(excl >> 1);
          while (uidx < need) { st2 = st2 * PCG_MULT() + inc; v2 = pcg_out(st2); ++uidx; }
          unsigned int u9 = (excl & 1) ? (uint32_t)(v2 >> 32) : (uint32_t)v2;
          g_group[excl] = (unsigned char)((u9 >> 31) * 6 + cnd[k]);
        }
        ++excl;
      }
    }
  }
}

DEV void cfg_bias_block(MainSmem* sm, int bi, int t) {
  u128 s0, inc; pcg_seed(s0, inc);
  const int PER = 20;
  int base = t * PER;
  unsigned char acc[PER];
  int cnt = 0;
  u128 st = pcg_advance(s0, inc, (uint64_t)(5000 + (base >> 1)) + 1);
  for (int k2 = 0; k2 < PER / 2; ++k2) {
    uint64_t v = pcg_out(st); st = st * PCG_MULT() + inc;
    int c0 = base + 2 * k2;
    unsigned long long m0 = (unsigned long long)(uint32_t)v * 6ull;
    unsigned long long m1 = (unsigned long long)(uint32_t)(v >> 32) * 6ull;
    unsigned char a0 = (c0 < 10048) && ((unsigned int)m0 >= 4u);
    unsigned char a1 = (c0 + 1 < 10048) && ((unsigned int)m1 >= 4u);
    acc[2 * k2] = a0; acc[2 * k2 + 1] = a1;
    cnt += a0 + a1;
  }
  int lane = t & 31, wid = t >> 5;
  int iv = cnt;
  for (int o = 1; o < 32; o <<= 1) {
    int n = __shfl_up_sync(0xffffffffu, iv, o);
    if (lane >= o) iv += n;
  }
  if (lane == 31) sm->rci[wid] = iv;
  __syncthreads();
  int woff = 0;
  for (int i = 0; i < wid; ++i) woff += sm->rci[i];
  int e0 = woff + iv - cnt;

  if (e0 < 10000 && e0 + cnt >= 10000) {   // this thread holds the 10000th accept
    int need = 10000 - e0, s = 0;
    for (int k = 0; k < PER; ++k) {
      s += acc[k];
      if (s == need) { sm->sel[0] = 10000 + base + k + 1; break; }  // total32
    }
  }
  __syncthreads();
  uint64_t D = ((uint64_t)sm->sel[0] + 1ull) >> 1;

  uint64_t k0 = ((uint64_t)bi * 512 + t) * 8;
  if (k0 < 10000) {
    u128 st3 = pcg_advance(s0, inc, D + k0 + 1);
#pragma unroll
    for (int m = 0; m < 8; ++m) {
      uint64_t i = k0 + m;
      if (i < 10000) {
        uint64_t u = pcg_out(st3);
        double dv = (double)(u >> 11) * (1.0 / 9007199254740992.0);
        g_bias[i] = (float)(-1.0 + 2.0 * dv);
      }
      st3 = st3 * PCG_MULT() + inc;
    }
  }
}

// ---------------- single fused kernel: 4 cfg blocks + 256 per-batch blocks ----------------
__global__ void __launch_bounds__(512, 2) main_kernel(const float* __restrict__ x,
                                                      float* __restrict__ out) {
  extern __shared__ __align__(128) char smem_raw[];
  MainSmem& sm = *(MainSmem*)smem_raw;
  int bid = blockIdx.x;
  int t = threadIdx.x, lane = t & 31, wid = t >> 5;

  if (bid < 4) {                       // cfg blocks scheduled first
    if (bid == 0) cfg_group_block(&sm, t);
    else cfg_bias_block(&sm, bid - 1, t);
    __syncthreads();
    __threadfence();
    if (t == 0) atomicAdd(&g_cfg_done, 1);
    return;
  }

  int b = bid - 4;

  // init smem
  if (t < 128) sm.S[t] = 0.f;
  else if (t < 256) sm.S[4224 + (t - 128)] = 0.f;
  if (t < 12) sm.cnt12[t] = 0;
  uint32_t mb0 = smem_u32(&sm.mbar[0]);
  if (t < 4) mbar_init(mb0 + 8 * t, 1);
  __syncthreads();

  // ---- bulk-async channel-sum: 4-stage cp.async.bulk pipeline ----
  {
    const float* src = x + (size_t)b * 23 * 4096;
    uint32_t stg0 = smem_u32(&sm.stage[0][0]);
    if (t == 0) {
#pragma unroll
      for (int c = 0; c < 4; ++c) {
        mbar_expect_tx(mb0 + 8 * c, 16384);
        bulk_copy(stg0 + c * 16384, src + c * 4096, 16384, mb0 + 8 * c);
      }
    }
    float4 acc0 = make_float4(0.f, 0.f, 0.f, 0.f);
    float4 acc1 = make_float4(0.f, 0.f, 0.f, 0.f);
    for (int c = 0; c < 23; ++c) {
      int s = c & 3;
      mbar_wait(mb0 + 8 * s, (c >> 2) & 1);
      const float4* st4 = (const float4*)sm.stage[s];
      f4add(acc0, st4[t]);
      f4add(acc1, st4[t + 512]);
      __syncthreads();                     // all consumed; slot reusable
      int nc = c + 4;
      if (nc < 23 && t == 0) {
        mbar_expect_tx(mb0 + 8 * s, 16384);
        bulk_copy(stg0 + s * 16384, src + nc * 4096, 16384, mb0 + 8 * s);
      }
    }
    ((float4*)(sm.S + 128))[t] = acc0;
    ((float4*)(sm.S + 128))[t + 512] = acc1;
  }
  __syncthreads();

  // all 6 dilations from smem
  for (int dexp = 0; dexp < 6; ++dexp)
    process_dilation(&sm, dexp, t, lane, wid);

  // wait for cfg (cfg blocks are wave-1 resident and long since done)
  if (t == 0) { while (atomicAdd(&g_cfg_done, 0) < 4) {} }
  __syncthreads();
  __threadfence();

  // write this batch's output slice
  for (int j = t; j < 5000; j += 512) {
    int i0 = 2 * j, i1 = i0 + 1;
    int g0 = g_group[i0], g1 = g_group[i1];
    float4 v;
    v.x = (sm.mres[g0] > g_bias[i0]) ? 1.0f : 0.0f;
    v.y = sm.tres[g0];
    v.z = (sm.mres[g1] > g_bias[i1]) ? 1.0f : 0.0f;
    v.w = sm.tres[g1];
    ((float4*)out)[(size_t)b * 5000 + j] = v;
  }
  if (t == 0) {
    int o2 = atomicAdd(&g_out_done, 1);
    if (o2 == 255) { g_out_done = 0; g_cfg_done = 0; }   // reset for replay
  }
}

extern "C" void kernel_launch(void* const* d_in, const int* in_sizes, int n_in,
                              void* d_out, int out_size) {
  const float* x = (const float*)d_in[0];
  float* out = (float*)d_out;
  int smem_bytes = (int)sizeof(MainSmem);
  cudaFuncSetAttribute(main_kernel, cudaFuncAttributeMaxDynamicSharedMemorySize,
                       smem_bytes);
  main_kernel<<<260, 512, smem_bytes>>>(x, out);
}

// round 17
// speedup vs baseline: 1.3685x; 1.3685x over previous
#include <cuda_runtime.h>
#include <cstdint>

#define DEV static __device__ __forceinline__
typedef unsigned __int128 u128;

__device__ unsigned char g_group[10000];
__device__ float g_bias[10000];
__device__ int g_cfg_done = 0;
__device__ int g_out_done = 0;

// ---------------- PCG64 (numpy default_rng) ----------------
DEV u128 PCG_MULT() {
  return (((u128)0x2360ED051FC65DA4ULL) << 64) | 0x4385DF649FCCF645ULL;
}
DEV uint32_t hashmix(uint32_t v, uint32_t& hc) {
  v ^= hc; hc *= 0x931e8875u; v *= hc; v ^= v >> 16; return v;
}
DEV uint32_t mix32(uint32_t x, uint32_t y) {
  uint32_t r = 0xca01f9ddu * x - 0x4973f715u * y; r ^= r >> 16; return r;
}
DEV void pcg_seed(u128& state, u128& inc) {
  uint32_t pool[4]; uint32_t hc = 0x43b0d7e5u;
  for (int i = 0; i < 4; ++i) pool[i] = hashmix(0u, hc);
  for (int s = 0; s < 4; ++s)
    for (int d2 = 0; d2 < 4; ++d2)
      if (s != d2) pool[d2] = mix32(pool[d2], hashmix(pool[s], hc));
  uint32_t hc2 = 0x8b51f9ddu; uint32_t w[8];
  for (int i = 0; i < 8; ++i) {
    uint32_t dv = pool[i & 3];
    dv ^= hc2; hc2 *= 0x58f38dedu; dv *= hc2; dv ^= dv >> 16; w[i] = dv;
  }
  u128 initstate = (((u128)((uint64_t)w[0] | ((uint64_t)w[1] << 32))) << 64) |
                   ((uint64_t)w[2] | ((uint64_t)w[3] << 32));
  u128 initseq   = (((u128)((uint64_t)w[4] | ((uint64_t)w[5] << 32))) << 64) |
                   ((uint64_t)w[6] | ((uint64_t)w[7] << 32));
  inc = (initseq << 1) | (u128)1;
  state = inc; state += initstate;
  state = state * PCG_MULT() + inc;
}
DEV u128 pcg_advance(u128 state, u128 inc, uint64_t delta) {
  u128 cm = PCG_MULT(), cp = inc, am = (u128)1, ap = (u128)0;
  while (delta) {
    if (delta & 1) { am = am * cm; ap = ap * cm + cp; }
    cp = (cm + (u128)1) * cp; cm = cm * cm; delta >>= 1;
  }
  return am * state + ap;
}
DEV uint64_t pcg_out(u128 st) {
  unsigned rot = (unsigned)(st >> 122);
  uint64_t x = (uint64_t)(st >> 64) ^ (uint64_t)st;
  return (x >> rot) | (x << ((64 - rot) & 63));
}

// ---------------- helpers ----------------
DEV void f4add(float4& a, const float4 v) {
  a.x += v.x; a.y += v.y; a.z += v.z; a.w += v.w;
}
DEV unsigned int f2ord(float f) {
  unsigned int b = __float_as_uint(f);
  return (b & 0x80000000u) ? ~b : (b | 0x80000000u);
}

// 512 threads, 8 elems/thread
template <int D>
DEV void conv2K(const float* S, int t, float* r7, float* r9) {
#pragma unroll
  for (int i = 0; i < 8; ++i) {
    int l = t + i * 512 + 128;
    float a = S[l - 3 * D];
    a += S[l - 2 * D]; a += S[l - D]; a += S[l]; a += S[l + D];
    a += S[l + 2 * D]; a += S[l + 3 * D];
    r7[i] = a;
    r9[i] = a + S[l - 4 * D] + S[l + 4 * D];
  }
}

struct MainSmem {
  float S[4352];            // pad128 | row 4096 | pad128 (never dirtied)
  unsigned int U[4096];     // fallback key buffer
  unsigned int hist[256];
  unsigned int wt[16];
  int sel[2];
  float redA[16], redB[16], sumA[16], sumB[16];
  float pivots[2];
  float mres[12], tres[12];
  int cnt12[12];
  int rci[16];
};

// cold exact path: radix-select rank 1351 over keys in U, then count(<=key);
// flag = count < 2704 i.e. v[1351] < v[2703]. 512 threads.
__device__ __noinline__ void fallback_select(unsigned int* U, unsigned int* hist,
                                             unsigned int* wt, int* sel, int* rci,
                                             int t, float* tres) {
  int lane = t & 31, wid = t >> 5;
  if (t < 256) hist[t] = 0;
  __syncthreads();
  for (int i = 0; i < 8; ++i)
    atomicAdd(&hist[U[t + i * 512] >> 24], 1u);
  __syncthreads();

#define SCAN_SELECT(rr)                                                        \
  {                                                                            \
    unsigned int oa = (t < 256) ? hist[t] : 0u; unsigned int a = oa;           \
    for (int o = 1; o < 32; o <<= 1) {                                         \
      unsigned int na = __shfl_up_sync(0xffffffffu, a, o);                     \
      if (lane >= o) a += na;                                                  \
    }                                                                          \
    if (lane == 31 && wid < 8) wt[wid] = a;                                    \
    __syncthreads();                                                           \
    if (wid == 0) {                                                            \
      unsigned int va = (lane < 8) ? wt[lane] : 0u;                            \
      for (int o = 1; o < 8; o <<= 1) {                                        \
        unsigned int na = __shfl_up_sync(0xffffffffu, va, o);                  \
        if (lane >= o) va += na;                                               \
      }                                                                        \
      if (lane < 8) wt[lane] = va;                                             \
    }                                                                          \
    __syncthreads();                                                           \
    if (t < 256) {                                                             \
      a += wid ? wt[wid - 1] : 0u;                                             \
      unsigned int lo = a - oa;                                                \
      if ((unsigned)(rr) >= lo && (unsigned)(rr) < a) { sel[0] = t; sel[1] = (int)lo; } \
    }                                                                          \
    __syncthreads();                                                           \
  }

  int rA = 1351; unsigned int pA = 0;
  SCAN_SELECT(rA);
  pA = ((unsigned int)sel[0]) << 24; rA -= sel[1];

  for (int p = 1; p < 4; ++p) {
    int shift = 24 - 8 * p;
    unsigned int maskHi = 0xFFFFFFFFu << (32 - 8 * p);
    if (t < 256) hist[t] = 0;
    __syncthreads();
    for (int i = 0; i < 8; ++i) {
      unsigned int key = U[t + i * 512];
      if (((key ^ pA) & maskHi) == 0)
        atomicAdd(&hist[(key >> shift) & 255u], 1u);
    }
    __syncthreads();
    SCAN_SELECT(rA);
    pA |= ((unsigned int)sel[0]) << shift; rA -= sel[1];
  }

  int cnt = 0;
  for (int i = 0; i < 8; ++i) cnt += (U[t + i * 512] <= pA) ? 1 : 0;
  for (int o = 16; o; o >>= 1) cnt += __shfl_xor_sync(0xffffffffu, cnt, o);
  if (lane == 0) rci[wid] = cnt;
  __syncthreads();
  if (t == 0) {
    int total = 0;
    for (int i = 0; i < 16; ++i) total += rci[i];
    *tres = (total < 2704) ? 1.0f : 0.0f;
  }
  __syncthreads();
#undef SCAN_SELECT
}

// hot path per dilation: conv -> warp reduce -> warp0 reduces the 16 partials
// and publishes max + pivot(mean) -> count(<=pivot) via shared atomics; count
// in [1352,2703] certifies v[1351] <= p < v[2703] => flag=1 exactly.
DEV void process_dilation(MainSmem* sm, int dexp, int t, int lane, int wid) {
  float* S = sm->S;
  float r7[8], r9[8];
  switch (dexp) {
    case 0:  conv2K<1>(S, t, r7, r9);  break;
    case 1:  conv2K<2>(S, t, r7, r9);  break;
    case 2:  conv2K<4>(S, t, r7, r9);  break;
    case 3:  conv2K<8>(S, t, r7, r9);  break;
    case 4:  conv2K<16>(S, t, r7, r9); break;
    default: conv2K<32>(S, t, r7, r9); break;
  }

  float mxA = r7[0], mxB = r9[0], smA = r7[0], smB = r9[0];
#pragma unroll
  for (int i = 1; i < 8; ++i) {
    mxA = fmaxf(mxA, r7[i]); smA += r7[i];
    mxB = fmaxf(mxB, r9[i]); smB += r9[i];
  }
  for (int o = 16; o; o >>= 1) {
    mxA = fmaxf(mxA, __shfl_xor_sync(0xffffffffu, mxA, o));
    mxB = fmaxf(mxB, __shfl_xor_sync(0xffffffffu, mxB, o));
    smA += __shfl_xor_sync(0xffffffffu, smA, o);
    smB += __shfl_xor_sync(0xffffffffu, smB, o);
  }
  if (lane == 0) {
    sm->redA[wid] = mxA; sm->redB[wid] = mxB;
    sm->sumA[wid] = smA; sm->sumB[wid] = smB;
  }
  __syncthreads();

  // warp 0 reduces the 16 partials and publishes results
  if (wid == 0) {
    float a = (lane < 16) ? sm->redA[lane] : -3.402823466e38f;
    float b = (lane < 16) ? sm->redB[lane] : -3.402823466e38f;
    float c = (lane < 16) ? sm->sumA[lane] : 0.f;
    float d = (lane < 16) ? sm->sumB[lane] : 0.f;
    for (int o = 8; o; o >>= 1) {
      a = fmaxf(a, __shfl_xor_sync(0xffffffffu, a, o));
      b = fmaxf(b, __shfl_xor_sync(0xffffffffu, b, o));
      c += __shfl_xor_sync(0xffffffffu, c, o);
      d += __shfl_xor_sync(0xffffffffu, d, o);
    }
    if (lane == 0) {
      sm->mres[dexp] = a; sm->mres[6 + dexp] = b;
      sm->pivots[0] = c * (1.0f / 4096.0f);
      sm->pivots[1] = d * (1.0f / 4096.0f);
    }
  }
  __syncthreads();

  float pA = sm->pivots[0], pB = sm->pivots[1];
  int cA = 0, cB = 0;
#pragma unroll
  for (int i = 0; i < 8; ++i) {
    cA += (r7[i] <= pA) ? 1 : 0;
    cB += (r9[i] <= pB) ? 1 : 0;
  }
  for (int o = 16; o; o >>= 1) {
    cA += __shfl_xor_sync(0xffffffffu, cA, o);
    cB += __shfl_xor_sync(0xffffffffu, cB, o);
  }
  if (lane == 0) {
    atomicAdd(&sm->cnt12[2 * dexp], cA);
    atomicAdd(&sm->cnt12[2 * dexp + 1], cB);
  }
  __syncthreads();

  int tA = sm->cnt12[2 * dexp], tB = sm->cnt12[2 * dexp + 1];
  bool okA = (tA >= 1352 && tA <= 2703);
  bool okB = (tB >= 1352 && tB <= 2703);
  if (t == 0) {
    if (okA) sm->tres[dexp] = 1.0f;
    if (okB) sm->tres[6 + dexp] = 1.0f;
  }
  if (okA && okB) return;

  if (!okA) {
#pragma unroll
    for (int i = 0; i < 8; ++i) sm->U[t + i * 512] = f2ord(r7[i]);
    __syncthreads();
    fallback_select(sm->U, sm->hist, sm->wt, sm->sel, sm->rci, t, &sm->tres[dexp]);
  }
  if (!okB) {
#pragma unroll
    for (int i = 0; i < 8; ++i) sm->U[t + i * 512] = f2ord(r9[i]);
    __syncthreads();
    fallback_select(sm->U, sm->hist, sm->wt, sm->sel, sm->rci, t, &sm->tres[6 + dexp]);
  }
}

// ---------------- self-contained config blocks (512 threads) ----------------
// Candidate c (0..10047) is u32 draw #(10000+c) => u64 #(5000+c/2), low first.
// Lemire rng_excl=6: accept iff low32(u*6) >= 4; value = hi32(u*6).
DEV void cfg_group_block(MainSmem* sm, int t) {
  u128 s0, inc; pcg_seed(s0, inc);
  const int PER = 20;
  int base = t * PER;
  unsigned char acc[PER], cnd[PER];
  int cnt = 0;
  u128 st = pcg_advance(s0, inc, (uint64_t)(5000 + (base >> 1)) + 1);
  for (int k2 = 0; k2 < PER / 2; ++k2) {
    uint64_t v = pcg_out(st); st = st * PCG_MULT() + inc;
    int c0 = base + 2 * k2;
    unsigned long long m0 = (unsigned long long)(uint32_t)v * 6ull;
    unsigned long long m1 = (unsigned long long)(uint32_t)(v >> 32) * 6ull;
    unsigned char a0 = (c0 < 10048) && ((unsigned int)m0 >= 4u);
    unsigned char a1 = (c0 + 1 < 10048) && ((unsigned int)m1 >= 4u);
    acc[2 * k2] = a0;     cnd[2 * k2] = (unsigned char)(m0 >> 32);
    acc[2 * k2 + 1] = a1; cnd[2 * k2 + 1] = (unsigned char)(m1 >> 32);
    cnt += a0 + a1;
  }
  int lane = t & 31, wid = t >> 5;
  int iv = cnt;
  for (int o = 1; o < 32; o <<= 1) {
    int n = __shfl_up_sync(0xffffffffu, iv, o);
    if (lane >= o) iv += n;
  }
  if (lane == 31) sm->rci[wid] = iv;
  __syncthreads();
  int woff = 0;
  for (int i = 0; i < wid; ++i) woff += sm->rci[i];
  int e0 = woff + iv - cnt;

  if (cnt > 0 && e0 < 10000) {
    uint64_t uidx = (uint64_t)(e0 >> 1);
    u128 st2 = pcg_advance(s0, inc, uidx + 1);
    uint64_t v2 = pcg_out(st2);
    int excl = e0;
    for (int k = 0; k < PER; ++k) {
      if (acc[k]) {
        if (excl < 10000) {
          uint64_t need = (uint64_t)(excl >> 1);
          while (uidx < need) { st2 = st2 * PCG_MULT() + inc; v2 = pcg_out(st2); ++uidx; }
          unsigned int u9 = (excl & 1) ? (uint32_t)(v2 >> 32) : (uint32_t)v2;
          g_group[excl] = (unsigned char)((u9 >> 31) * 6 + cnd[k]);
        }
        ++excl;
      }
    }
  }
}

DEV void cfg_bias_block(MainSmem* sm, int bi, int t) {
  u128 s0, inc; pcg_seed(s0, inc);
  const int PER = 20;
  int base = t * PER;
  unsigned char acc[PER];
  int cnt = 0;
  u128 st = pcg_advance(s0, inc, (uint64_t)(5000 + (base >> 1)) + 1);
  for (int k2 = 0; k2 < PER / 2; ++k2) {
    uint64_t v = pcg_out(st); st = st * PCG_MULT() + inc;
    int c0 = base + 2 * k2;
    unsigned long long m0 = (unsigned long long)(uint32_t)v * 6ull;
    unsigned long long m1 = (unsigned long long)(uint32_t)(v >> 32) * 6ull;
    unsigned char a0 = (c0 < 10048) && ((unsigned int)m0 >= 4u);
    unsigned char a1 = (c0 + 1 < 10048) && ((unsigned int)m1 >= 4u);
    acc[2 * k2] = a0; acc[2 * k2 + 1] = a1;
    cnt += a0 + a1;
  }
  int lane = t & 31, wid = t >> 5;
  int iv = cnt;
  for (int o = 1; o < 32; o <<= 1) {
    int n = __shfl_up_sync(0xffffffffu, iv, o);
    if (lane >= o) iv += n;
  }
  if (lane == 31) sm->rci[wid] = iv;
  __syncthreads();
  int woff = 0;
  for (int i = 0; i < wid; ++i) woff += sm->rci[i];
  int e0 = woff + iv - cnt;

  if (e0 < 10000 && e0 + cnt >= 10000) {   // this thread holds the 10000th accept
    int need = 10000 - e0, s = 0;
    for (int k = 0; k < PER; ++k) {
      s += acc[k];
      if (s == need) { sm->sel[0] = 10000 + base + k + 1; break; }  // total32
    }
  }
  __syncthreads();
  uint64_t D = ((uint64_t)sm->sel[0] + 1ull) >> 1;

  uint64_t k0 = ((uint64_t)bi * 512 + t) * 8;
  if (k0 < 10000) {
    u128 st3 = pcg_advance(s0, inc, D + k0 + 1);
#pragma unroll
    for (int m = 0; m < 8; ++m) {
      uint64_t i = k0 + m;
      if (i < 10000) {
        uint64_t u = pcg_out(st3);
        double dv = (double)(u >> 11) * (1.0 / 9007199254740992.0);
        g_bias[i] = (float)(-1.0 + 2.0 * dv);
      }
      st3 = st3 * PCG_MULT() + inc;
    }
  }
}

// ---------------- single fused kernel: 4 cfg blocks + 256 per-batch blocks ----------------
__global__ void __launch_bounds__(512, 2) main_kernel(const float* __restrict__ x,
                                                      float* __restrict__ out) {
  __shared__ __align__(16) MainSmem sm;
  int bid = blockIdx.x;
  int t = threadIdx.x, lane = t & 31, wid = t >> 5;

  if (bid < 4) {                       // cfg blocks scheduled first
    if (bid == 0) cfg_group_block(&sm, t);
    else cfg_bias_block(&sm, bid - 1, t);
    __syncthreads();
    __threadfence();
    if (t == 0) atomicAdd(&g_cfg_done, 1);
    return;
  }

  int b = bid - 4;

  // init smem
  if (t < 128) sm.S[t] = 0.f;
  else if (t < 256) sm.S[4224 + (t - 128)] = 0.f;
  if (t < 12) sm.cnt12[t] = 0;

  // load + channel-sum this batch's x row into S.
  // 8-load batches (4 channels x 2 columns), 4 accumulator chains -> high MLP.
  {
    const float4* xb = (const float4*)x + (size_t)b * 23 * 1024;
    int c0 = t, c1 = t + 512;
    float4 a0 = __ldcs(xb + c0);
    float4 b0 = __ldcs(xb + c1);
    float4 a1 = __ldcs(xb + 1024 + c0);
    float4 b1 = __ldcs(xb + 1024 + c1);
#pragma unroll
    for (int c = 2; c < 22; c += 4) {
      float4 va0 = __ldcs(xb + (size_t)c * 1024 + c0);
      float4 vb0 = __ldcs(xb + (size_t)c * 1024 + c1);
      float4 va1 = __ldcs(xb + (size_t)(c + 1) * 1024 + c0);
      float4 vb1 = __ldcs(xb + (size_t)(c + 1) * 1024 + c1);
      float4 va2 = __ldcs(xb + (size_t)(c + 2) * 1024 + c0);
      float4 vb2 = __ldcs(xb + (size_t)(c + 2) * 1024 + c1);
      float4 va3 = __ldcs(xb + (size_t)(c + 3) * 1024 + c0);
      float4 vb3 = __ldcs(xb + (size_t)(c + 3) * 1024 + c1);
      f4add(a0, va0); f4add(b0, vb0);
      f4add(a1, va1); f4add(b1, vb1);
      f4add(a0, va2); f4add(b0, vb2);
      f4add(a1, va3); f4add(b1, vb3);
    }
    f4add(a0, __ldcs(xb + (size_t)22 * 1024 + c0));
    f4add(b0, __ldcs(xb + (size_t)22 * 1024 + c1));
    f4add(a0, a1); f4add(b0, b1);
    ((float4*)(sm.S + 128))[c0] = a0;
    ((float4*)(sm.S + 128))[c1] = b0;
  }
  __syncthreads();

  // all 6 dilations from smem
  for (int dexp = 0; dexp < 6; ++dexp)
    process_dilation(&sm, dexp, t, lane, wid);

  // wait for cfg (cfg blocks are wave-1 resident and long since done)
  if (t == 0) { while (atomicAdd(&g_cfg_done, 0) < 4) {} }
  __syncthreads();
  __threadfence();

  // write this batch's output slice
  for (int j = t; j < 5000; j += 512) {
    int i0 = 2 * j, i1 = i0 + 1;
    int g0 = g_group[i0], g1 = g_group[i1];
    float4 v;
    v.x = (sm.mres[g0] > g_bias[i0]) ? 1.0f : 0.0f;
    v.y = sm.tres[g0];
    v.z = (sm.mres[g1] > g_bias[i1]) ? 1.0f : 0.0f;
    v.w = sm.tres[g1];
    ((float4*)out)[(size_t)b * 5000 + j] = v;
  }
  if (t == 0) {
    int o2 = atomicAdd(&g_out_done, 1);
    if (o2 == 255) { g_out_done = 0; g_cfg_done = 0; }   // reset for replay
  }
}

extern "C" void kernel_launch(void* const* d_in, const int* in_sizes, int n_in,
                              void* d_out, int out_size) {
  const float* x = (const float*)d_in[0];
  float* out = (float*)d_out;
  main_kernel<<<260, 512>>>(x, out);
}